// round 1
// baseline (speedup 1.0000x reference)
#include <cuda_runtime.h>
#include <cstdint>

// ---------------------------------------------------------------------------
// HDSLinear: out = x @ (W * nm_mask(scores, noise))^T + bias
//   x:      [B*S, D_IN]  fp32   (M x K)
//   W:      [D_OUT, D_IN] fp32  (N x K)
//   mask:   exact 2-of-4 per group along D_IN (gumbel top-2, forward = y_hard)
// Phase 1: build masked weight (tf32-rounded) into device scratch.
// Phase 2: TF32 tensor-core GEMM (m16n8k8 mma.sync), 128x128x16 tiles.
// ---------------------------------------------------------------------------

#define EPSV 1e-10f

// 64MB scratch for masked weight (D_OUT x D_IN = 4096 x 4096 fp32)
__device__ float g_wm[4096u * 4096u];

__device__ __forceinline__ uint32_t f2tf32(float f) {
    uint32_t r;
    asm("cvt.rna.tf32.f32 %0, %1;" : "=r"(r) : "f"(f));
    return r;
}

__device__ __forceinline__ float4 cvt4_tf32(float4 v) {
    v.x = __uint_as_float(f2tf32(v.x));
    v.y = __uint_as_float(f2tf32(v.y));
    v.z = __uint_as_float(f2tf32(v.z));
    v.w = __uint_as_float(f2tf32(v.w));
    return v;
}

// -------------------- Phase 1: mask + weight --------------------
__global__ void __launch_bounds__(256) mask_weight_kernel(
    const float* __restrict__ w,
    const float* __restrict__ scores,
    const float* __restrict__ noise,
    int ngroups)
{
    int g = blockIdx.x * blockDim.x + threadIdx.x;
    if (g >= ngroups) return;

    float4 s4 = __ldg(((const float4*)scores) + g);
    float4 u4 = __ldg(((const float4*)noise) + g);
    float s[4] = {s4.x, s4.y, s4.z, s4.w};
    float u[4] = {u4.x, u4.y, u4.z, u4.w};
    float y[4];
#pragma unroll
    for (int i = 0; i < 4; i++) {
        // gumbel = -log(-log(u + eps) + eps); TEMP = 1
        y[i] = s[i] - logf(-logf(u[i] + EPSV) + EPSV);
    }
    // top-2 with jax top_k tie-break (first occurrence wins)
    int i1 = 0;
#pragma unroll
    for (int i = 1; i < 4; i++) if (y[i] > y[i1]) i1 = i;
    int i2 = (i1 == 0) ? 1 : 0;
#pragma unroll
    for (int i = 0; i < 4; i++)
        if (i != i1 && i != i2 && y[i] > y[i2]) i2 = i;

    float4 w4 = __ldg(((const float4*)w) + g);
    float wv[4] = {w4.x, w4.y, w4.z, w4.w};
    float o[4];
#pragma unroll
    for (int i = 0; i < 4; i++)
        o[i] = (i == i1 || i == i2) ? __uint_as_float(f2tf32(wv[i])) : 0.0f;

    ((float4*)g_wm)[g] = make_float4(o[0], o[1], o[2], o[3]);
}

// -------------------- Phase 2: TF32 GEMM --------------------
#define BM 128
#define BN 128
#define BK 16
#define LDSD (BK + 4)   // 20 floats: (20*r + c) mod 32 is conflict-free for frags

__global__ void __launch_bounds__(256, 1) gemm_tf32_kernel(
    const float* __restrict__ A,     // [M, K] x
    const float* __restrict__ bias,  // [N]
    float* __restrict__ C,           // [M, N]
    int M, int N, int K)
{
    __shared__ float As[2][BM * LDSD];
    __shared__ float Bs[2][BN * LDSD];

    const float* __restrict__ B = g_wm;  // [N, K] tf32-rounded masked weight

    const int tid  = threadIdx.x;
    const int lane = tid & 31;
    const int warp = tid >> 5;
    const int wm   = warp >> 2;   // 0..1  (M direction, 64 rows each)
    const int wn   = warp & 3;    // 0..3  (N direction, 32 cols each)

    const long bm = (long)blockIdx.y * BM;
    const long bn = (long)blockIdx.x * BN;

    // global->smem staging: thread loads rows lr, lr+64; 4 floats at col lc
    const int lr = tid >> 2;           // 0..63
    const int lc = (tid & 3) << 2;     // 0,4,8,12

    const float* Ag = A + (bm + lr) * (long)K + lc;
    const float* Bg = B + (bn + lr) * (long)K + lc;

    float acc[4][4][4];
#pragma unroll
    for (int mt = 0; mt < 4; mt++)
#pragma unroll
        for (int nt = 0; nt < 4; nt++)
#pragma unroll
            for (int i = 0; i < 4; i++) acc[mt][nt][i] = 0.0f;

    // prologue: tile 0
    float4 ra0 = *(const float4*)(Ag);
    float4 ra1 = *(const float4*)(Ag + (long)64 * K);
    float4 rb0 = *(const float4*)(Bg);
    float4 rb1 = *(const float4*)(Bg + (long)64 * K);

    *(float4*)&As[0][lr * LDSD + lc]        = cvt4_tf32(ra0);
    *(float4*)&As[0][(lr + 64) * LDSD + lc] = cvt4_tf32(ra1);
    *(float4*)&Bs[0][lr * LDSD + lc]        = rb0;   // already tf32-rounded
    *(float4*)&Bs[0][(lr + 64) * LDSD + lc] = rb1;
    __syncthreads();

    const int nk = K / BK;
    for (int kt = 0; kt < nk; kt++) {
        const int cur = kt & 1;

        // prefetch next tile into registers (overlaps with compute below)
        if (kt + 1 < nk) {
            const float* Ap = Ag + (kt + 1) * BK;
            const float* Bp = Bg + (kt + 1) * BK;
            ra0 = *(const float4*)(Ap);
            ra1 = *(const float4*)(Ap + (long)64 * K);
            rb0 = *(const float4*)(Bp);
            rb1 = *(const float4*)(Bp + (long)64 * K);
        }

        const float* __restrict__ asm_ = &As[cur][0];
        const float* __restrict__ bsm_ = &Bs[cur][0];

#pragma unroll
        for (int ks = 0; ks < BK / 8; ks++) {
            uint32_t af[4][4], bf[4][2];
            const int acol = ks * 8 + (lane & 3);
            const int arow = wm * 64 + (lane >> 2);
#pragma unroll
            for (int mt = 0; mt < 4; mt++) {
                int r = arow + mt * 16;
                af[mt][0] = __float_as_uint(asm_[r * LDSD + acol]);
                af[mt][1] = __float_as_uint(asm_[(r + 8) * LDSD + acol]);
                af[mt][2] = __float_as_uint(asm_[r * LDSD + acol + 4]);
                af[mt][3] = __float_as_uint(asm_[(r + 8) * LDSD + acol + 4]);
            }
            const int brow = wn * 32 + (lane >> 2);
#pragma unroll
            for (int nt = 0; nt < 4; nt++) {
                int r = brow + nt * 8;
                bf[nt][0] = __float_as_uint(bsm_[r * LDSD + acol]);
                bf[nt][1] = __float_as_uint(bsm_[r * LDSD + acol + 4]);
            }
#pragma unroll
            for (int mt = 0; mt < 4; mt++) {
#pragma unroll
                for (int nt = 0; nt < 4; nt++) {
                    asm volatile(
                        "mma.sync.aligned.m16n8k8.row.col.f32.tf32.tf32.f32 "
                        "{%0,%1,%2,%3}, {%4,%5,%6,%7}, {%8,%9}, {%0,%1,%2,%3};"
                        : "+f"(acc[mt][nt][0]), "+f"(acc[mt][nt][1]),
                          "+f"(acc[mt][nt][2]), "+f"(acc[mt][nt][3])
                        : "r"(af[mt][0]), "r"(af[mt][1]),
                          "r"(af[mt][2]), "r"(af[mt][3]),
                          "r"(bf[nt][0]), "r"(bf[nt][1]));
                }
            }
        }

        if (kt + 1 < nk) {
            const int nxt = cur ^ 1;
            *(float4*)&As[nxt][lr * LDSD + lc]        = cvt4_tf32(ra0);
            *(float4*)&As[nxt][(lr + 64) * LDSD + lc] = cvt4_tf32(ra1);
            *(float4*)&Bs[nxt][lr * LDSD + lc]        = rb0;
            *(float4*)&Bs[nxt][(lr + 64) * LDSD + lc] = rb1;
            __syncthreads();
        }
    }

    // epilogue: add bias, store
#pragma unroll
    for (int mt = 0; mt < 4; mt++) {
        long row = bm + wm * 64 + mt * 16 + (lane >> 2);
#pragma unroll
        for (int nt = 0; nt < 4; nt++) {
            long col = bn + wn * 32 + nt * 8 + (lane & 3) * 2;
            float b0 = __ldg(&bias[col]);
            float b1 = __ldg(&bias[col + 1]);
            float2 v0 = make_float2(acc[mt][nt][0] + b0, acc[mt][nt][1] + b1);
            float2 v1 = make_float2(acc[mt][nt][2] + b0, acc[mt][nt][3] + b1);
            *(float2*)&C[row * N + col]       = v0;
            *(float2*)&C[(row + 8) * N + col] = v1;
        }
    }
}

// -------------------- launch --------------------
extern "C" void kernel_launch(void* const* d_in, const int* in_sizes, int n_in,
                              void* d_out, int out_size)
{
    const float* x      = (const float*)d_in[0];
    const float* weight = (const float*)d_in[1];
    const float* bias   = (const float*)d_in[2];
    const float* scores = (const float*)d_in[3];
    const float* noise  = (const float*)d_in[4];
    float* out = (float*)d_out;

    const int D_OUT = in_sizes[2];                 // 4096
    const int D_IN  = in_sizes[1] / D_OUT;         // 4096
    const int M     = in_sizes[0] / D_IN;          // 16384 (B*S)
    const int ngroups = in_sizes[1] / 4;           // D_OUT * G

    mask_weight_kernel<<<(ngroups + 255) / 256, 256>>>(weight, scores, noise, ngroups);

    dim3 grid(D_OUT / BN, M / BM);  // x-fastest: CTAs sharing an A tile run together
    gemm_tf32_kernel<<<grid, 256>>>(x, bias, out, M, D_OUT, D_IN);
}

// round 3
// speedup vs baseline: 1.9598x; 1.9598x over previous
#include <cuda_runtime.h>
#include <cstdint>

// ---------------------------------------------------------------------------
// HDSLinear (sm_103, HMMA path — tcgen05 unavailable: harness builds compute_103):
//   out[M,N] = x[M,K] @ (W*mask)[N,K]^T + bias,  M=16384, N=K=4096
// pack_x : tf32-round x, repack into per-thread A-fragment order.
// pack_w : gumbel top-2-of-4 mask + tf32 round W, repack into B-fragment order.
// gemm   : 128x128x32 tiles, 4 warps (2x2, 64x64 warp tile), 3-stage cp.async,
//          mma.sync.m16n8k8.tf32, fragment loads are LDS.128/LDS.64.
// ---------------------------------------------------------------------------

#define EPSV 1e-10f

constexpr int KD = 4096;
constexpr int ND = 4096;
constexpr int BM = 128;
constexpr int BN = 128;
constexpr int BK = 32;
constexpr int NKT = KD / BK;          // 128 k-tiles
constexpr int STAGES = 3;
constexpr int A_STAGE_B = BM * BK * 4;   // 16384 bytes
constexpr int B_STAGE_B = BN * BK * 4;   // 16384 bytes
constexpr int STAGE_B = A_STAGE_B + B_STAGE_B;  // 32768
constexpr int SMEM_GEMM = STAGES * STAGE_B;     // 98304

// packed operands:
// g_xp: [M/128][NKT][ ks(4) wm(2) mt(4) lane(32) ] float4
// g_wp: [N/128][NKT][ ks(4) wn(2) nt(8) lane(32) ] float2
__device__ float4 g_xp[(16384 / 128) * (size_t)NKT * 1024];
__device__ float2 g_wp[(4096 / 128) * (size_t)NKT * 2048];

// ----------------------------- helpers ------------------------------------
__device__ __forceinline__ uint32_t f2tf32(float f) {
    uint32_t r;
    asm("cvt.rna.tf32.f32 %0, %1;" : "=r"(r) : "f"(f));
    return r;
}
__device__ __forceinline__ float4 cvt4_tf32(float4 v) {
    v.x = __uint_as_float(f2tf32(v.x));
    v.y = __uint_as_float(f2tf32(v.y));
    v.z = __uint_as_float(f2tf32(v.z));
    v.w = __uint_as_float(f2tf32(v.w));
    return v;
}
__device__ __forceinline__ uint32_t smem_u32(const void* p) {
    uint32_t a;
    asm("{ .reg .u64 t; cvta.to.shared.u64 t, %1; cvt.u32.u64 %0, t; }"
        : "=r"(a) : "l"(p));
    return a;
}

#define CP_ASYNC_16(dst, src) \
    asm volatile("cp.async.ca.shared.global [%0], [%1], 16;" \
                 :: "r"(dst), "l"(src) : "memory")
#define CP_COMMIT() asm volatile("cp.async.commit_group;" ::: "memory")
#define CP_WAIT1()  asm volatile("cp.async.wait_group 1;"  ::: "memory")

// -------------------- pack_x: round + fragment repack ----------------------
// grid (NKT, M/128), 256 threads. smem stride 36 -> conflict-free gathers.
__global__ void __launch_bounds__(256) pack_x(const float* __restrict__ x)
{
    __shared__ float s[128 * 36];
    const int mb = blockIdx.y, kt = blockIdx.x, tid = threadIdx.x;
    const float* xb = x + ((size_t)mb * 128) * KD + kt * BK;

#pragma unroll
    for (int i = 0; i < 4; i++) {
        int idx = i * 256 + tid;
        int row = idx >> 3;
        int c4  = idx & 7;
        float4 v = __ldg((const float4*)(xb + (size_t)row * KD + c4 * 4));
        v = cvt4_tf32(v);
        float* d = &s[row * 36 + c4 * 4];
        d[0] = v.x; d[1] = v.y; d[2] = v.z; d[3] = v.w;
    }
    __syncthreads();

    float4* out = g_xp + ((size_t)mb * NKT + kt) * 1024;
#pragma unroll
    for (int i = 0; i < 4; i++) {
        int o  = i * 256 + tid;
        int ks = o >> 8, wm = (o >> 7) & 1, mt = (o >> 5) & 3, ln = o & 31;
        int r = wm * 64 + mt * 16 + (ln >> 2);
        int c = ks * 8 + (ln & 3);
        float4 v;
        v.x = s[r * 36 + c];
        v.y = s[(r + 8) * 36 + c];
        v.z = s[r * 36 + c + 4];
        v.w = s[(r + 8) * 36 + c + 4];
        out[o] = v;
    }
}

// -------------------- pack_w: mask + round + repack ------------------------
// grid (NKT, ND/128), 256 threads. Each float4 chunk == exactly one 4-group.
__global__ void __launch_bounds__(256) pack_w(
    const float* __restrict__ w,
    const float* __restrict__ sc,
    const float* __restrict__ nu)
{
    __shared__ float s[128 * 36];
    const int nb = blockIdx.y, kt = blockIdx.x, tid = threadIdx.x;
    const size_t base = ((size_t)nb * 128) * KD + kt * BK;

#pragma unroll
    for (int i = 0; i < 4; i++) {
        int idx = i * 256 + tid;
        int row = idx >> 3;
        int c4  = idx & 7;
        size_t off = base + (size_t)row * KD + c4 * 4;
        float4 w4 = __ldg((const float4*)(w + off));
        float4 s4 = __ldg((const float4*)(sc + off));
        float4 u4 = __ldg((const float4*)(nu + off));

        float sv[4] = {s4.x, s4.y, s4.z, s4.w};
        float uv[4] = {u4.x, u4.y, u4.z, u4.w};
        float y[4];
#pragma unroll
        for (int j = 0; j < 4; j++)
            y[j] = sv[j] - logf(-logf(uv[j] + EPSV) + EPSV);

        // top-2, first occurrence wins on ties (jax top_k semantics)
        int i1 = 0;
#pragma unroll
        for (int j = 1; j < 4; j++) if (y[j] > y[i1]) i1 = j;
        int i2 = (i1 == 0) ? 1 : 0;
#pragma unroll
        for (int j = 0; j < 4; j++)
            if (j != i1 && j != i2 && y[j] > y[i2]) i2 = j;

        float wv[4] = {w4.x, w4.y, w4.z, w4.w};
        float* d = &s[row * 36 + c4 * 4];
#pragma unroll
        for (int j = 0; j < 4; j++)
            d[j] = (j == i1 || j == i2) ? __uint_as_float(f2tf32(wv[j])) : 0.0f;
    }
    __syncthreads();

    float2* out = g_wp + ((size_t)nb * NKT + kt) * 2048;
#pragma unroll
    for (int i = 0; i < 8; i++) {
        int o  = i * 256 + tid;
        int ks = o >> 9, wn = (o >> 8) & 1, nt = (o >> 5) & 7, ln = o & 31;
        int r = wn * 64 + nt * 8 + (ln >> 2);
        int c = ks * 8 + (ln & 3);
        out[o] = make_float2(s[r * 36 + c], s[r * 36 + c + 4]);
    }
}

// ------------------------------- GEMM --------------------------------------
__global__ void __launch_bounds__(128) gemm_kernel(
    const float* __restrict__ bias,
    float* __restrict__ C)
{
    extern __shared__ char smem[];
    const uint32_t sb = smem_u32(smem);
    const int tid  = threadIdx.x;
    const int warp = tid >> 5;
    const int lane = tid & 31;
    const int wm   = warp >> 1;   // 0..1 -> 64 M rows
    const int wn   = warp & 1;    // 0..1 -> 64 N cols

    const int nb = blockIdx.x;
    const int mb = blockIdx.y;

    const char* pA = (const char*)(g_xp + (size_t)mb * NKT * 1024);
    const char* pB = (const char*)(g_wp + (size_t)nb * NKT * 2048);

    float acc[4][8][4];
#pragma unroll
    for (int mt = 0; mt < 4; mt++)
#pragma unroll
        for (int nt = 0; nt < 8; nt++)
#pragma unroll
            for (int i = 0; i < 4; i++) acc[mt][nt][i] = 0.0f;

    // issue stage copy: 8 x 16B per thread per operand
#define ISSUE(st, kt) do {                                                    \
    uint32_t _dA = sb + (st) * STAGE_B;                                       \
    uint32_t _dB = _dA + A_STAGE_B;                                           \
    const char* _sA = pA + (size_t)(kt) * A_STAGE_B;                          \
    const char* _sB = pB + (size_t)(kt) * B_STAGE_B;                          \
    _Pragma("unroll")                                                         \
    for (int _j = 0; _j < 8; _j++) {                                          \
        int _i = _j * 128 + tid;                                              \
        CP_ASYNC_16(_dA + _i * 16, _sA + _i * 16);                            \
        CP_ASYNC_16(_dB + _i * 16, _sB + _i * 16);                            \
    }                                                                         \
    CP_COMMIT();                                                              \
} while (0)

    ISSUE(0, 0);
    ISSUE(1, 1);

    for (int kt = 0; kt < NKT; kt++) {
        CP_WAIT1();
        __syncthreads();
        if (kt + 2 < NKT) {
            int st = kt + 2 - ((kt + 2) / 3) * 3;
            ISSUE(st, kt + 2);
        }
        const int cur = kt - (kt / 3) * 3;
        const float4* As = (const float4*)(smem + cur * STAGE_B);
        const float2* Bs = (const float2*)(smem + cur * STAGE_B + A_STAGE_B);

#pragma unroll
        for (int ks = 0; ks < 4; ks++) {
            uint32_t af[4][4], bf[8][2];
#pragma unroll
            for (int mt = 0; mt < 4; mt++) {
                float4 v = As[((ks * 2 + wm) * 4 + mt) * 32 + lane];
                af[mt][0] = __float_as_uint(v.x);
                af[mt][1] = __float_as_uint(v.y);
                af[mt][2] = __float_as_uint(v.z);
                af[mt][3] = __float_as_uint(v.w);
            }
#pragma unroll
            for (int nt = 0; nt < 8; nt++) {
                float2 v = Bs[((ks * 2 + wn) * 8 + nt) * 32 + lane];
                bf[nt][0] = __float_as_uint(v.x);
                bf[nt][1] = __float_as_uint(v.y);
            }
#pragma unroll
            for (int mt = 0; mt < 4; mt++) {
#pragma unroll
                for (int nt = 0; nt < 8; nt++) {
                    asm volatile(
                        "mma.sync.aligned.m16n8k8.row.col.f32.tf32.tf32.f32 "
                        "{%0,%1,%2,%3}, {%4,%5,%6,%7}, {%8,%9}, {%0,%1,%2,%3};"
                        : "+f"(acc[mt][nt][0]), "+f"(acc[mt][nt][1]),
                          "+f"(acc[mt][nt][2]), "+f"(acc[mt][nt][3])
                        : "r"(af[mt][0]), "r"(af[mt][1]),
                          "r"(af[mt][2]), "r"(af[mt][3]),
                          "r"(bf[nt][0]), "r"(bf[nt][1]));
                }
            }
        }
    }

    // epilogue
    const long bmr = (long)mb * BM;
    const long bnc = (long)nb * BN;
#pragma unroll
    for (int mt = 0; mt < 4; mt++) {
        long row = bmr + wm * 64 + mt * 16 + (lane >> 2);
        float* c0 = C + row * (long)ND;
        float* c1 = C + (row + 8) * (long)ND;
#pragma unroll
        for (int nt = 0; nt < 8; nt++) {
            long col = bnc + wn * 64 + nt * 8 + (lane & 3) * 2;
            float b0 = __ldg(&bias[col]);
            float b1 = __ldg(&bias[col + 1]);
            *(float2*)(c0 + col) = make_float2(acc[mt][nt][0] + b0,
                                               acc[mt][nt][1] + b1);
            *(float2*)(c1 + col) = make_float2(acc[mt][nt][2] + b0,
                                               acc[mt][nt][3] + b1);
        }
    }
#undef ISSUE
}

// ----------------------------- launch --------------------------------------
extern "C" void kernel_launch(void* const* d_in, const int* in_sizes, int n_in,
                              void* d_out, int out_size)
{
    const float* x      = (const float*)d_in[0];
    const float* weight = (const float*)d_in[1];
    const float* bias   = (const float*)d_in[2];
    const float* scores = (const float*)d_in[3];
    const float* noise  = (const float*)d_in[4];
    float* out = (float*)d_out;

    const int M = in_sizes[0] / KD;   // 16384

    cudaFuncSetAttribute(gemm_kernel,
                         cudaFuncAttributeMaxDynamicSharedMemorySize, SMEM_GEMM);

    pack_x<<<dim3(NKT, M / 128), 256>>>(x);
    pack_w<<<dim3(NKT, ND / 128), 256>>>(weight, scores, noise);

    dim3 grid(ND / BN, M / BM);       // 32 x 128, x-fastest shares A panel
    gemm_kernel<<<grid, 128, SMEM_GEMM>>>(bias, out);
}

// round 4
// speedup vs baseline: 2.0245x; 1.0330x over previous
#include <cuda_runtime.h>
#include <cstdint>

// ---------------------------------------------------------------------------
// HDSLinear (sm_103 SIMT HMMA path):
//   out[M,N] = x[M,K] @ (W*mask)[N,K]^T + bias,  M=16384, N=K=4096
// pack_x : tf32-round x, repack into per-thread A-fragment order.
// pack_w : gumbel top-2-of-4 mask + tf32 round W, repack into B-fragment order.
// gemm   : 128x128x32 tiles, 8 warps (4x2, 32x64 warp tile), 3-stage cp.async.cg,
//          mma.sync.m16n8k8.tf32. 2 CTAs/SM -> 16 warps/SM for latency hiding.
// ---------------------------------------------------------------------------

#define EPSV 1e-10f

constexpr int KD = 4096;
constexpr int ND = 4096;
constexpr int BM = 128;
constexpr int BN = 128;
constexpr int BK = 32;
constexpr int NKT = KD / BK;          // 128 k-tiles
constexpr int A_STAGE_B = BM * BK * 4;   // 16384 bytes
constexpr int B_STAGE_B = BN * BK * 4;   // 16384 bytes
constexpr int STAGE_B = A_STAGE_B + B_STAGE_B;  // 32768
constexpr int SMEM_GEMM = 3 * STAGE_B;          // 98304

// packed operands:
// g_xp: [M/128][NKT][ ks(4) wm(4) mt(2) lane(32) ] float4
// g_wp: [N/128][NKT][ ks(4) wn(2) nt(8) lane(32) ] float2
__device__ float4 g_xp[(16384 / 128) * (size_t)NKT * 1024];
__device__ float2 g_wp[(4096 / 128) * (size_t)NKT * 2048];

// ----------------------------- helpers ------------------------------------
__device__ __forceinline__ uint32_t f2tf32(float f) {
    uint32_t r;
    asm("cvt.rna.tf32.f32 %0, %1;" : "=r"(r) : "f"(f));
    return r;
}
__device__ __forceinline__ float4 cvt4_tf32(float4 v) {
    v.x = __uint_as_float(f2tf32(v.x));
    v.y = __uint_as_float(f2tf32(v.y));
    v.z = __uint_as_float(f2tf32(v.z));
    v.w = __uint_as_float(f2tf32(v.w));
    return v;
}
__device__ __forceinline__ uint32_t smem_u32(const void* p) {
    uint32_t a;
    asm("{ .reg .u64 t; cvta.to.shared.u64 t, %1; cvt.u32.u64 %0, t; }"
        : "=r"(a) : "l"(p));
    return a;
}

#define CP_ASYNC_16(dst, src) \
    asm volatile("cp.async.cg.shared.global [%0], [%1], 16;" \
                 :: "r"(dst), "l"(src) : "memory")
#define CP_COMMIT() asm volatile("cp.async.commit_group;" ::: "memory")
#define CP_WAIT1()  asm volatile("cp.async.wait_group 1;"  ::: "memory")

// -------------------- pack_x: round + fragment repack ----------------------
// grid (NKT, M/128), 256 threads. smem stride 36 -> conflict-free gathers.
__global__ void __launch_bounds__(256) pack_x(const float* __restrict__ x)
{
    __shared__ float s[128 * 36];
    const int mb = blockIdx.y, kt = blockIdx.x, tid = threadIdx.x;
    const float* xb = x + ((size_t)mb * 128) * KD + kt * BK;

#pragma unroll
    for (int i = 0; i < 4; i++) {
        int idx = i * 256 + tid;
        int row = idx >> 3;
        int c4  = idx & 7;
        float4 v = __ldg((const float4*)(xb + (size_t)row * KD + c4 * 4));
        v = cvt4_tf32(v);
        float* d = &s[row * 36 + c4 * 4];
        d[0] = v.x; d[1] = v.y; d[2] = v.z; d[3] = v.w;
    }
    __syncthreads();

    float4* out = g_xp + ((size_t)mb * NKT + kt) * 1024;
#pragma unroll
    for (int i = 0; i < 4; i++) {
        int o  = i * 256 + tid;
        int ks = o >> 8, wm = (o >> 6) & 3, mt = (o >> 5) & 1, ln = o & 31;
        int r = wm * 32 + mt * 16 + (ln >> 2);
        int c = ks * 8 + (ln & 3);
        float4 v;
        v.x = s[r * 36 + c];
        v.y = s[(r + 8) * 36 + c];
        v.z = s[r * 36 + c + 4];
        v.w = s[(r + 8) * 36 + c + 4];
        out[o] = v;
    }
}

// -------------------- pack_w: mask + round + repack ------------------------
// grid (NKT, ND/128), 256 threads. Each float4 chunk == exactly one 4-group.
__global__ void __launch_bounds__(256) pack_w(
    const float* __restrict__ w,
    const float* __restrict__ sc,
    const float* __restrict__ nu)
{
    __shared__ float s[128 * 36];
    const int nb = blockIdx.y, kt = blockIdx.x, tid = threadIdx.x;
    const size_t base = ((size_t)nb * 128) * KD + kt * BK;

#pragma unroll
    for (int i = 0; i < 4; i++) {
        int idx = i * 256 + tid;
        int row = idx >> 3;
        int c4  = idx & 7;
        size_t off = base + (size_t)row * KD + c4 * 4;
        float4 w4 = __ldg((const float4*)(w + off));
        float4 s4 = __ldg((const float4*)(sc + off));
        float4 u4 = __ldg((const float4*)(nu + off));

        float sv[4] = {s4.x, s4.y, s4.z, s4.w};
        float uv[4] = {u4.x, u4.y, u4.z, u4.w};
        float y[4];
#pragma unroll
        for (int j = 0; j < 4; j++)
            y[j] = sv[j] - logf(-logf(uv[j] + EPSV) + EPSV);

        // top-2, first occurrence wins on ties (jax top_k semantics)
        int i1 = 0;
#pragma unroll
        for (int j = 1; j < 4; j++) if (y[j] > y[i1]) i1 = j;
        int i2 = (i1 == 0) ? 1 : 0;
#pragma unroll
        for (int j = 0; j < 4; j++)
            if (j != i1 && j != i2 && y[j] > y[i2]) i2 = j;

        float wv[4] = {w4.x, w4.y, w4.z, w4.w};
        float* d = &s[row * 36 + c4 * 4];
#pragma unroll
        for (int j = 0; j < 4; j++)
            d[j] = (j == i1 || j == i2) ? __uint_as_float(f2tf32(wv[j])) : 0.0f;
    }
    __syncthreads();

    float2* out = g_wp + ((size_t)nb * NKT + kt) * 2048;
#pragma unroll
    for (int i = 0; i < 8; i++) {
        int o  = i * 256 + tid;
        int ks = o >> 9, wn = (o >> 8) & 1, nt = (o >> 5) & 7, ln = o & 31;
        int r = wn * 64 + nt * 8 + (ln >> 2);
        int c = ks * 8 + (ln & 3);
        out[o] = make_float2(s[r * 36 + c], s[r * 36 + c + 4]);
    }
}

// ------------------------------- GEMM --------------------------------------
__global__ void __launch_bounds__(256, 2) gemm_kernel(
    const float* __restrict__ bias,
    float* __restrict__ C)
{
    extern __shared__ char smem[];
    const uint32_t sb = smem_u32(smem);
    const int tid  = threadIdx.x;
    const int warp = tid >> 5;
    const int lane = tid & 31;
    const int wm   = warp >> 1;   // 0..3 -> 32 M rows
    const int wn   = warp & 1;    // 0..1 -> 64 N cols

    const int nb = blockIdx.x;
    const int mb = blockIdx.y;

    const char* pA = (const char*)(g_xp + (size_t)mb * NKT * 1024);
    const char* pB = (const char*)(g_wp + (size_t)nb * NKT * 2048);

    float acc[2][8][4];
#pragma unroll
    for (int mt = 0; mt < 2; mt++)
#pragma unroll
        for (int nt = 0; nt < 8; nt++)
#pragma unroll
            for (int i = 0; i < 4; i++) acc[mt][nt][i] = 0.0f;

    // issue stage copy: 4 x 16B per thread per operand (256 threads)
#define ISSUE(st, kt) do {                                                    \
    uint32_t _dA = sb + (st) * STAGE_B;                                       \
    uint32_t _dB = _dA + A_STAGE_B;                                           \
    const char* _sA = pA + (size_t)(kt) * A_STAGE_B;                          \
    const char* _sB = pB + (size_t)(kt) * B_STAGE_B;                          \
    _Pragma("unroll")                                                         \
    for (int _j = 0; _j < 4; _j++) {                                          \
        int _i = _j * 256 + tid;                                              \
        CP_ASYNC_16(_dA + _i * 16, _sA + _i * 16);                            \
        CP_ASYNC_16(_dB + _i * 16, _sB + _i * 16);                            \
    }                                                                         \
    CP_COMMIT();                                                              \
} while (0)

    ISSUE(0, 0);
    ISSUE(1, 1);

    for (int kt = 0; kt < NKT; kt++) {
        CP_WAIT1();
        __syncthreads();
        if (kt + 2 < NKT) {
            int st = kt + 2 - ((kt + 2) / 3) * 3;
            ISSUE(st, kt + 2);
        }
        const int cur = kt - (kt / 3) * 3;
        const float4* As = (const float4*)(smem + cur * STAGE_B);
        const float2* Bs = (const float2*)(smem + cur * STAGE_B + A_STAGE_B);

#pragma unroll
        for (int ks = 0; ks < 4; ks++) {
            uint32_t af[2][4], bf[8][2];
#pragma unroll
            for (int mt = 0; mt < 2; mt++) {
                float4 v = As[((ks * 4 + wm) * 2 + mt) * 32 + lane];
                af[mt][0] = __float_as_uint(v.x);
                af[mt][1] = __float_as_uint(v.y);
                af[mt][2] = __float_as_uint(v.z);
                af[mt][3] = __float_as_uint(v.w);
            }
#pragma unroll
            for (int nt = 0; nt < 8; nt++) {
                float2 v = Bs[((ks * 2 + wn) * 8 + nt) * 32 + lane];
                bf[nt][0] = __float_as_uint(v.x);
                bf[nt][1] = __float_as_uint(v.y);
            }
#pragma unroll
            for (int mt = 0; mt < 2; mt++) {
#pragma unroll
                for (int nt = 0; nt < 8; nt++) {
                    asm volatile(
                        "mma.sync.aligned.m16n8k8.row.col.f32.tf32.tf32.f32 "
                        "{%0,%1,%2,%3}, {%4,%5,%6,%7}, {%8,%9}, {%0,%1,%2,%3};"
                        : "+f"(acc[mt][nt][0]), "+f"(acc[mt][nt][1]),
                          "+f"(acc[mt][nt][2]), "+f"(acc[mt][nt][3])
                        : "r"(af[mt][0]), "r"(af[mt][1]),
                          "r"(af[mt][2]), "r"(af[mt][3]),
                          "r"(bf[nt][0]), "r"(bf[nt][1]));
                }
            }
        }
    }

    // epilogue
    const long bmr = (long)mb * BM;
    const long bnc = (long)nb * BN;
#pragma unroll
    for (int mt = 0; mt < 2; mt++) {
        long row = bmr + wm * 32 + mt * 16 + (lane >> 2);
        float* c0 = C + row * (long)ND;
        float* c1 = C + (row + 8) * (long)ND;
#pragma unroll
        for (int nt = 0; nt < 8; nt++) {
            long col = bnc + wn * 64 + nt * 8 + (lane & 3) * 2;
            float b0 = __ldg(&bias[col]);
            float b1 = __ldg(&bias[col + 1]);
            *(float2*)(c0 + col) = make_float2(acc[mt][nt][0] + b0,
                                               acc[mt][nt][1] + b1);
            *(float2*)(c1 + col) = make_float2(acc[mt][nt][2] + b0,
                                               acc[mt][nt][3] + b1);
        }
    }
#undef ISSUE
}

// ----------------------------- launch --------------------------------------
extern "C" void kernel_launch(void* const* d_in, const int* in_sizes, int n_in,
                              void* d_out, int out_size)
{
    const float* x      = (const float*)d_in[0];
    const float* weight = (const float*)d_in[1];
    const float* bias   = (const float*)d_in[2];
    const float* scores = (const float*)d_in[3];
    const float* noise  = (const float*)d_in[4];
    float* out = (float*)d_out;

    const int M = in_sizes[0] / KD;   // 16384

    cudaFuncSetAttribute(gemm_kernel,
                         cudaFuncAttributeMaxDynamicSharedMemorySize, SMEM_GEMM);

    pack_x<<<dim3(NKT, M / 128), 256>>>(x);
    pack_w<<<dim3(NKT, ND / 128), 256>>>(weight, scores, noise);

    dim3 grid(ND / BN, M / BM);       // 32 x 128, x-fastest shares A panel
    gemm_kernel<<<grid, 256, SMEM_GEMM>>>(bias, out);
}

// round 5
// speedup vs baseline: 3.7422x; 1.8484x over previous
#include <cuda_runtime.h>
#include <cuda_fp16.h>
#include <cstdint>

// ---------------------------------------------------------------------------
// HDSLinear (sm_103 SIMT HMMA path, fp16 inputs / fp32 accum):
//   out[M,N] = x[M,K] @ (W*mask)[N,K]^T + bias,  M=16384, N=K=4096
// pack_x : x -> fp16, repack into per-thread A-fragment order (m16n8k16).
// pack_w : gumbel top-2-of-4 mask, W -> fp16, B-fragment order.
// gemm   : 128x128x32 tiles, 8 warps (4x2, 32x64 warp tile), 4-stage
//          cp.async.cg, mma.sync.m16n8k16.f16 (2x FLOPs/inst vs tf32).
// ---------------------------------------------------------------------------

#define EPSV 1e-10f

constexpr int KD = 4096;
constexpr int ND = 4096;
constexpr int BM = 128;
constexpr int BN = 128;
constexpr int BK = 32;
constexpr int NKT = KD / BK;             // 128 k-tiles
constexpr int A_STAGE_B = BM * BK * 2;   // 8192 bytes (fp16)
constexpr int B_STAGE_B = BN * BK * 2;   // 8192 bytes
constexpr int STAGE_B = A_STAGE_B + B_STAGE_B;  // 16384
constexpr int STAGES = 4;
constexpr int SMEM_GEMM = STAGES * STAGE_B;     // 65536

// packed operands (fragment order for m16n8k16):
// g_xp: [M/128][NKT][ ks(2) wm(4) mt(2) lane(32) ] uint4  (8 halves)
// g_wp: [N/128][NKT][ ks(2) wn(2) nt(8) lane(32) ] uint2  (4 halves)
__device__ uint4 g_xp[(16384 / 128) * (size_t)NKT * 512];
__device__ uint2 g_wp[(4096 / 128) * (size_t)NKT * 1024];

// ----------------------------- helpers ------------------------------------
__device__ __forceinline__ uint32_t packh2(float lo, float hi) {
    __half2 h = __floats2half2_rn(lo, hi);
    return *(uint32_t*)&h;
}
__device__ __forceinline__ uint32_t smem_u32(const void* p) {
    uint32_t a;
    asm("{ .reg .u64 t; cvta.to.shared.u64 t, %1; cvt.u32.u64 %0, t; }"
        : "=r"(a) : "l"(p));
    return a;
}

#define CP_ASYNC_16(dst, src) \
    asm volatile("cp.async.cg.shared.global [%0], [%1], 16;" \
                 :: "r"(dst), "l"(src) : "memory")
#define CP_COMMIT() asm volatile("cp.async.commit_group;" ::: "memory")
#define CP_WAIT2()  asm volatile("cp.async.wait_group 2;"  ::: "memory")

// -------------------- pack_x: fp16 + fragment repack -----------------------
// grid (NKT, M/128), 256 threads. smem stride 36 -> conflict-light gathers.
__global__ void __launch_bounds__(256) pack_x(const float* __restrict__ x)
{
    __shared__ float s[128 * 36];
    const int mb = blockIdx.y, kt = blockIdx.x, tid = threadIdx.x;
    const float* xb = x + ((size_t)mb * 128) * KD + kt * BK;

#pragma unroll
    for (int i = 0; i < 4; i++) {
        int idx = i * 256 + tid;
        int row = idx >> 3;
        int c4  = idx & 7;
        float4 v = __ldg((const float4*)(xb + (size_t)row * KD + c4 * 4));
        float* d = &s[row * 36 + c4 * 4];
        d[0] = v.x; d[1] = v.y; d[2] = v.z; d[3] = v.w;
    }
    __syncthreads();

    uint4* out = g_xp + ((size_t)mb * NKT + kt) * 512;
#pragma unroll
    for (int i = 0; i < 2; i++) {
        int o  = i * 256 + tid;                 // 512 fragments
        int ks = o >> 8, wm = (o >> 6) & 3, mt = (o >> 5) & 1, ln = o & 31;
        int g = ln >> 2, t = ln & 3;
        int r = wm * 32 + mt * 16 + g;
        int c = ks * 16 + 2 * t;
        uint4 v;
        v.x = packh2(s[r * 36 + c],           s[r * 36 + c + 1]);
        v.y = packh2(s[(r + 8) * 36 + c],     s[(r + 8) * 36 + c + 1]);
        v.z = packh2(s[r * 36 + c + 8],       s[r * 36 + c + 9]);
        v.w = packh2(s[(r + 8) * 36 + c + 8], s[(r + 8) * 36 + c + 9]);
        out[o] = v;
    }
}

// -------------------- pack_w: mask + fp16 + repack --------------------------
// grid (NKT, ND/128), 256 threads. Each float4 chunk == exactly one 4-group.
__global__ void __launch_bounds__(256) pack_w(
    const float* __restrict__ w,
    const float* __restrict__ sc,
    const float* __restrict__ nu)
{
    __shared__ float s[128 * 36];
    const int nb = blockIdx.y, kt = blockIdx.x, tid = threadIdx.x;
    const size_t base = ((size_t)nb * 128) * KD + kt * BK;

#pragma unroll
    for (int i = 0; i < 4; i++) {
        int idx = i * 256 + tid;
        int row = idx >> 3;
        int c4  = idx & 7;
        size_t off = base + (size_t)row * KD + c4 * 4;
        float4 w4 = __ldg((const float4*)(w + off));
        float4 s4 = __ldg((const float4*)(sc + off));
        float4 u4 = __ldg((const float4*)(nu + off));

        float sv[4] = {s4.x, s4.y, s4.z, s4.w};
        float uv[4] = {u4.x, u4.y, u4.z, u4.w};
        float y[4];
#pragma unroll
        for (int j = 0; j < 4; j++)
            y[j] = sv[j] - logf(-logf(uv[j] + EPSV) + EPSV);

        // top-2, first occurrence wins on ties (jax top_k semantics)
        int i1 = 0;
#pragma unroll
        for (int j = 1; j < 4; j++) if (y[j] > y[i1]) i1 = j;
        int i2 = (i1 == 0) ? 1 : 0;
#pragma unroll
        for (int j = 0; j < 4; j++)
            if (j != i1 && j != i2 && y[j] > y[i2]) i2 = j;

        float wv[4] = {w4.x, w4.y, w4.z, w4.w};
        float* d = &s[row * 36 + c4 * 4];
#pragma unroll
        for (int j = 0; j < 4; j++)
            d[j] = (j == i1 || j == i2) ? wv[j] : 0.0f;
    }
    __syncthreads();

    uint2* out = g_wp + ((size_t)nb * NKT + kt) * 1024;
#pragma unroll
    for (int i = 0; i < 4; i++) {
        int o  = i * 256 + tid;                 // 1024 fragments
        int ks = o >> 9, wn = (o >> 8) & 1, nt = (o >> 5) & 7, ln = o & 31;
        int g = ln >> 2, t = ln & 3;
        int n = wn * 64 + nt * 8 + g;
        int c = ks * 16 + 2 * t;
        uint2 v;
        v.x = packh2(s[n * 36 + c],     s[n * 36 + c + 1]);
        v.y = packh2(s[n * 36 + c + 8], s[n * 36 + c + 9]);
        out[o] = v;
    }
}

// ------------------------------- GEMM --------------------------------------
__global__ void __launch_bounds__(256, 2) gemm_kernel(
    const float* __restrict__ bias,
    float* __restrict__ C)
{
    extern __shared__ char smem[];
    const uint32_t sb = smem_u32(smem);
    const int tid  = threadIdx.x;
    const int warp = tid >> 5;
    const int lane = tid & 31;
    const int wm   = warp >> 1;   // 0..3 -> 32 M rows
    const int wn   = warp & 1;    // 0..1 -> 64 N cols

    const int nb = blockIdx.x;
    const int mb = blockIdx.y;

    const char* pA = (const char*)(g_xp + (size_t)mb * NKT * 512);
    const char* pB = (const char*)(g_wp + (size_t)nb * NKT * 1024);

    float acc[2][8][4];
#pragma unroll
    for (int mt = 0; mt < 2; mt++)
#pragma unroll
        for (int nt = 0; nt < 8; nt++)
#pragma unroll
            for (int i = 0; i < 4; i++) acc[mt][nt][i] = 0.0f;

    // issue stage copy: 2 x 16B per thread per operand (256 threads, 16KB)
#define ISSUE(st, kt) do {                                                    \
    uint32_t _dA = sb + (st) * STAGE_B;                                       \
    uint32_t _dB = _dA + A_STAGE_B;                                           \
    const char* _sA = pA + (size_t)(kt) * A_STAGE_B;                          \
    const char* _sB = pB + (size_t)(kt) * B_STAGE_B;                          \
    _Pragma("unroll")                                                         \
    for (int _j = 0; _j < 2; _j++) {                                          \
        int _i = _j * 256 + tid;                                              \
        CP_ASYNC_16(_dA + _i * 16, _sA + _i * 16);                            \
        CP_ASYNC_16(_dB + _i * 16, _sB + _i * 16);                            \
    }                                                                         \
    CP_COMMIT();                                                              \
} while (0)

    ISSUE(0, 0);
    ISSUE(1, 1);
    ISSUE(2, 2);

    for (int kt = 0; kt < NKT; kt++) {
        CP_WAIT2();
        __syncthreads();
        if (kt + 3 < NKT) ISSUE((kt + 3) & 3, kt + 3);

        const int cur = kt & 3;
        const uint4* As = (const uint4*)(smem + cur * STAGE_B);
        const uint2* Bs = (const uint2*)(smem + cur * STAGE_B + A_STAGE_B);

#pragma unroll
        for (int ks = 0; ks < 2; ks++) {
            uint4 af[2];
            uint2 bf[8];
#pragma unroll
            for (int mt = 0; mt < 2; mt++)
                af[mt] = As[((ks * 4 + wm) * 2 + mt) * 32 + lane];
#pragma unroll
            for (int nt = 0; nt < 8; nt++)
                bf[nt] = Bs[((ks * 2 + wn) * 8 + nt) * 32 + lane];
#pragma unroll
            for (int mt = 0; mt < 2; mt++) {
#pragma unroll
                for (int nt = 0; nt < 8; nt++) {
                    asm volatile(
                        "mma.sync.aligned.m16n8k16.row.col.f32.f16.f16.f32 "
                        "{%0,%1,%2,%3}, {%4,%5,%6,%7}, {%8,%9}, {%0,%1,%2,%3};"
                        : "+f"(acc[mt][nt][0]), "+f"(acc[mt][nt][1]),
                          "+f"(acc[mt][nt][2]), "+f"(acc[mt][nt][3])
                        : "r"(af[mt].x), "r"(af[mt].y),
                          "r"(af[mt].z), "r"(af[mt].w),
                          "r"(bf[nt].x), "r"(bf[nt].y));
                }
            }
        }
    }

    // epilogue
    const long bmr = (long)mb * BM;
    const long bnc = (long)nb * BN;
#pragma unroll
    for (int mt = 0; mt < 2; mt++) {
        long row = bmr + wm * 32 + mt * 16 + (lane >> 2);
        float* c0 = C + row * (long)ND;
        float* c1 = C + (row + 8) * (long)ND;
#pragma unroll
        for (int nt = 0; nt < 8; nt++) {
            long col = bnc + wn * 64 + nt * 8 + (lane & 3) * 2;
            float b0 = __ldg(&bias[col]);
            float b1 = __ldg(&bias[col + 1]);
            *(float2*)(c0 + col) = make_float2(acc[mt][nt][0] + b0,
                                               acc[mt][nt][1] + b1);
            *(float2*)(c1 + col) = make_float2(acc[mt][nt][2] + b0,
                                               acc[mt][nt][3] + b1);
        }
    }
#undef ISSUE
}

// ----------------------------- launch --------------------------------------
extern "C" void kernel_launch(void* const* d_in, const int* in_sizes, int n_in,
                              void* d_out, int out_size)
{
    const float* x      = (const float*)d_in[0];
    const float* weight = (const float*)d_in[1];
    const float* bias   = (const float*)d_in[2];
    const float* scores = (const float*)d_in[3];
    const float* noise  = (const float*)d_in[4];
    float* out = (float*)d_out;

    const int M = in_sizes[0] / KD;   // 16384

    cudaFuncSetAttribute(gemm_kernel,
                         cudaFuncAttributeMaxDynamicSharedMemorySize, SMEM_GEMM);

    pack_x<<<dim3(NKT, M / 128), 256>>>(x);
    pack_w<<<dim3(NKT, ND / 128), 256>>>(weight, scores, noise);

    dim3 grid(ND / BN, M / BM);       // 32 x 128, x-fastest shares A panel
    gemm_kernel<<<grid, 256, SMEM_GEMM>>>(bias, out);
}

// round 6
// speedup vs baseline: 4.9628x; 1.3262x over previous
#include <cuda_runtime.h>
#include <cuda_fp16.h>
#include <cstdint>

// ---------------------------------------------------------------------------
// HDSLinear (sm_103, 2:4 SPARSE HMMA path):
//   out[M,N] = x[M,K] @ (W*mask)[N,K]^T + bias,  M=16384, N=K=4096
// Computed as out^T = Wm @ x^T with mma.sp (A = compressed Wm, 2:4 along K).
// pack_x : x -> fp16 B-fragments of x^T (m16n8k32 col-major B).
// pack_w : gumbel top-2-of-4; compress kept pairs -> A-fragments + metadata.
// gemm   : 128(N) x 128(M) x 32 tiles, 8 warps, 4-stage cp.async.cg,
//          mma.sp::ordered_metadata.m16n8k32 (2x FLOP/inst vs dense k16),
//          smem-transpose epilogue with coalesced stores + bias.
// ---------------------------------------------------------------------------

#define EPSV 1e-10f

constexpr int KD = 4096;
constexpr int ND = 4096;
constexpr int NKT = KD / 32;             // 128 k-chunks of 32
constexpr int A_ST = 4096;               // compressed W: 128 rows x 16 halves
constexpr int E_ST = 1024;               // metadata: 256 x u32 (half used)
constexpr int B_ST = 8192;               // x^T: 32k x 128m halves
constexpr int STAGE_B = A_ST + E_ST + B_ST;   // 13312
constexpr int SMEM_GEMM = 4 * STAGE_B;        // 53248

// fragment panels
__device__ uint4    g_xp[128ull * NKT * 512];   // [mb][kc][jm(16)*32+lane]
__device__ uint4    g_wa[32ull * NKT * 256];    // [nb][kc][jn(8)*32+lane]
__device__ uint32_t g_we[32ull * NKT * 256];    // metadata, same indexing

// ----------------------------- helpers ------------------------------------
__device__ __forceinline__ uint32_t packh2(float lo, float hi) {
    __half2 h = __floats2half2_rn(lo, hi);
    return *(uint32_t*)&h;
}
__device__ __forceinline__ uint32_t smem_u32(const void* p) {
    uint32_t a;
    asm("{ .reg .u64 t; cvta.to.shared.u64 t, %1; cvt.u32.u64 %0, t; }"
        : "=r"(a) : "l"(p));
    return a;
}

#define CP_ASYNC_16(dst, src) \
    asm volatile("cp.async.cg.shared.global [%0], [%1], 16;" \
                 :: "r"(dst), "l"(src) : "memory")
#define CP_COMMIT() asm volatile("cp.async.commit_group;" ::: "memory")
#define CP_WAIT2()  asm volatile("cp.async.wait_group 2;"  ::: "memory")
#define CP_WAIT0()  asm volatile("cp.async.wait_group 0;"  ::: "memory")

// -------------------- pack_x: x^T B-fragments ------------------------------
// grid (NKT, M/128), 256 threads.
// B frag (m16n8k32 col): col m = jm*8 + (lane>>2); b_i = x[m][kb+2t+8i, +1].
__global__ void __launch_bounds__(256) pack_x(const float* __restrict__ x)
{
    __shared__ float s[128 * 36];
    const int mb = blockIdx.y, kt = blockIdx.x, tid = threadIdx.x;
    const float* xb = x + ((size_t)mb * 128) * KD + kt * 32;

#pragma unroll
    for (int i = 0; i < 4; i++) {
        int idx = i * 256 + tid;
        int row = idx >> 3;
        int c4  = idx & 7;
        float4 v = __ldg((const float4*)(xb + (size_t)row * KD + c4 * 4));
        float* d = &s[row * 36 + c4 * 4];
        d[0] = v.x; d[1] = v.y; d[2] = v.z; d[3] = v.w;
    }
    __syncthreads();

    uint4* out = g_xp + ((size_t)mb * NKT + kt) * 512;
#pragma unroll
    for (int i = 0; i < 2; i++) {
        int o  = i * 256 + tid;             // 512 fragments
        int jm = o >> 5, ln = o & 31;
        int g = ln >> 2, t = ln & 3;
        const float* r = &s[(jm * 8 + g) * 36 + 2 * t];
        uint4 v;
        v.x = packh2(r[0],  r[1]);
        v.y = packh2(r[8],  r[9]);
        v.z = packh2(r[16], r[17]);
        v.w = packh2(r[24], r[25]);
        out[o] = v;
    }
}

// -------------------- pack_w: mask + compress + meta ------------------------
// grid (NKT, ND/128), 256 threads.
__global__ void __launch_bounds__(256) pack_w(
    const float* __restrict__ w,
    const float* __restrict__ sc,
    const float* __restrict__ nu)
{
    __shared__ __half comp[128 * 18];      // compressed halves, stride 18
    __shared__ uint8_t metb[128 * 8];      // nibble per (row, group)
    const int nb = blockIdx.y, kt = blockIdx.x, tid = threadIdx.x;
    const size_t base = ((size_t)nb * 128) * KD + kt * 32;

#pragma unroll
    for (int i = 0; i < 4; i++) {
        int idx = i * 256 + tid;            // 1024 chunks = (row, group)
        int row = idx >> 3;
        int grp = idx & 7;
        size_t off = base + (size_t)row * KD + grp * 4;
        float4 w4 = __ldg((const float4*)(w + off));
        float4 s4 = __ldg((const float4*)(sc + off));
        float4 u4 = __ldg((const float4*)(nu + off));

        float sv[4] = {s4.x, s4.y, s4.z, s4.w};
        float uv[4] = {u4.x, u4.y, u4.z, u4.w};
        float y[4];
#pragma unroll
        for (int j = 0; j < 4; j++)
            y[j] = sv[j] - logf(-logf(uv[j] + EPSV) + EPSV);

        // top-2, first occurrence wins on ties (jax top_k semantics)
        int i1 = 0;
#pragma unroll
        for (int j = 1; j < 4; j++) if (y[j] > y[i1]) i1 = j;
        int i2 = (i1 == 0) ? 1 : 0;
#pragma unroll
        for (int j = 0; j < 4; j++)
            if (j != i1 && j != i2 && y[j] > y[i2]) i2 = j;

        int lo = min(i1, i2), hi = max(i1, i2);
        float wv[4] = {w4.x, w4.y, w4.z, w4.w};
        *(__half2*)&comp[row * 18 + grp * 2] =
            __floats2half2_rn(wv[lo], wv[hi]);
        metb[row * 8 + grp] = (uint8_t)(lo | (hi << 2));
    }
    __syncthreads();

    // A fragments: compressed 16x16 per (jn, k32), dense-m16n8k16 layout
    {
        int jn = tid >> 5, ln = tid & 31;
        int g = ln >> 2, t = ln & 3;
        int r0 = jn * 16 + g, r8 = r0 + 8;
        uint4 v;
        v.x = *(const uint32_t*)&comp[r0 * 18 + 2 * t];
        v.y = *(const uint32_t*)&comp[r8 * 18 + 2 * t];
        v.z = *(const uint32_t*)&comp[r0 * 18 + 2 * t + 8];
        v.w = *(const uint32_t*)&comp[r8 * 18 + 2 * t + 8];
        g_wa[((size_t)nb * NKT + kt) * 256 + tid] = v;

        // metadata: lane%4==0 -> k-groups 0..3, ==1 -> 4..7; low16=row g,
        // high16=row g+8; nibble = idx0 | idx1<<2 (ascending).
        uint32_t e = 0;
        if (t < 2) {
            int gb = t * 4;
            uint32_t lo16 = (uint32_t)metb[r0 * 8 + gb]
                          | ((uint32_t)metb[r0 * 8 + gb + 1] << 4)
                          | ((uint32_t)metb[r0 * 8 + gb + 2] << 8)
                          | ((uint32_t)metb[r0 * 8 + gb + 3] << 12);
            uint32_t hi16 = (uint32_t)metb[r8 * 8 + gb]
                          | ((uint32_t)metb[r8 * 8 + gb + 1] << 4)
                          | ((uint32_t)metb[r8 * 8 + gb + 2] << 8)
                          | ((uint32_t)metb[r8 * 8 + gb + 3] << 12);
            e = lo16 | (hi16 << 16);
        }
        g_we[((size_t)nb * NKT + kt) * 256 + tid] = e;
    }
}

// ------------------------------- GEMM --------------------------------------
// out^T tile: 128 N-rows x 128 M-cols. 8 warps: wn=warp>>1 (2 jn tiles),
// wm=warp&1 (8 jm tiles). Per warp-iter: 2 at x 8 bt mma.sp (k32 each).
__global__ void __launch_bounds__(256, 2) gemm_kernel(
    const float* __restrict__ bias,
    float* __restrict__ C)
{
    extern __shared__ char smem[];
    const uint32_t sb = smem_u32(smem);
    const int tid  = threadIdx.x;
    const int warp = tid >> 5;
    const int lane = tid & 31;
    const int wn   = warp >> 1;   // 0..3 -> 32 N rows
    const int wm   = warp & 1;    // 0..1 -> 64 M cols
    const int g    = lane >> 2;
    const int t    = lane & 3;

    const int nb = blockIdx.x;
    const int mb = blockIdx.y;

    const char* pA = (const char*)(g_wa + (size_t)nb * NKT * 256);
    const char* pE = (const char*)(g_we + (size_t)nb * NKT * 256);
    const char* pB = (const char*)(g_xp + (size_t)mb * NKT * 512);

    float acc[2][8][4];
#pragma unroll
    for (int at = 0; at < 2; at++)
#pragma unroll
        for (int bt = 0; bt < 8; bt++)
#pragma unroll
            for (int i = 0; i < 4; i++) acc[at][bt][i] = 0.0f;

#define ISSUE(st, kt) do {                                                    \
    uint32_t _d = sb + (st) * STAGE_B;                                        \
    CP_ASYNC_16(_d + tid * 16, pA + (size_t)(kt) * A_ST + tid * 16);          \
    if (tid < 64)                                                             \
        CP_ASYNC_16(_d + A_ST + tid * 16, pE + (size_t)(kt) * E_ST + tid * 16);\
    _Pragma("unroll")                                                         \
    for (int _j = 0; _j < 2; _j++) {                                          \
        int _i = _j * 256 + tid;                                              \
        CP_ASYNC_16(_d + A_ST + E_ST + _i * 16,                               \
                    pB + (size_t)(kt) * B_ST + _i * 16);                      \
    }                                                                         \
    CP_COMMIT();                                                              \
} while (0)

    ISSUE(0, 0);
    ISSUE(1, 1);
    ISSUE(2, 2);

    for (int kt = 0; kt < NKT; kt++) {
        CP_WAIT2();
        __syncthreads();
        if (kt + 3 < NKT) ISSUE((kt + 3) & 3, kt + 3);

        const char* st = smem + (kt & 3) * STAGE_B;
        const uint4*    As = (const uint4*)st;
        const uint32_t* Es = (const uint32_t*)(st + A_ST);
        const uint4*    Bs = (const uint4*)(st + A_ST + E_ST);

        uint4 af[2];
        uint32_t ea[2];
#pragma unroll
        for (int at = 0; at < 2; at++) {
            af[at] = As[(wn * 2 + at) * 32 + lane];
            ea[at] = Es[(wn * 2 + at) * 32 + lane];
        }
#pragma unroll
        for (int bt = 0; bt < 8; bt++) {
            uint4 bf = Bs[(wm * 8 + bt) * 32 + lane];
#pragma unroll
            for (int at = 0; at < 2; at++) {
                asm volatile(
                    "mma.sp::ordered_metadata.sync.aligned.m16n8k32."
                    "row.col.f32.f16.f16.f32 "
                    "{%0,%1,%2,%3}, {%4,%5,%6,%7}, {%8,%9,%10,%11}, "
                    "{%0,%1,%2,%3}, %12, 0x0;"
                    : "+f"(acc[at][bt][0]), "+f"(acc[at][bt][1]),
                      "+f"(acc[at][bt][2]), "+f"(acc[at][bt][3])
                    : "r"(af[at].x), "r"(af[at].y),
                      "r"(af[at].z), "r"(af[at].w),
                      "r"(bf.x), "r"(bf.y), "r"(bf.z), "r"(bf.w),
                      "r"(ea[at]));
            }
        }
    }
#undef ISSUE

    // ---- epilogue: per-warp smem transpose, coalesced stores + bias ----
    CP_WAIT0();
    __syncthreads();

    const int n0 = nb * 128 + wn * 32;
    const float bv = __ldg(&bias[n0 + lane]);
    float* wbuf = (float*)(smem + warp * 4224);   // 32 x 33 floats

#pragma unroll
    for (int p = 0; p < 2; p++) {
#pragma unroll
        for (int at = 0; at < 2; at++) {
#pragma unroll
            for (int b2 = 0; b2 < 4; b2++) {
                int bt = p * 4 + b2;
                int mrow = b2 * 8 + 2 * t;
                int ncol = at * 16 + g;
                wbuf[mrow * 33 + ncol]           = acc[at][bt][0];
                wbuf[(mrow + 1) * 33 + ncol]     = acc[at][bt][1];
                wbuf[mrow * 33 + ncol + 8]       = acc[at][bt][2];
                wbuf[(mrow + 1) * 33 + ncol + 8] = acc[at][bt][3];
            }
        }
        __syncwarp();
        long gmr = (long)mb * 128 + wm * 64 + p * 32;
#pragma unroll
        for (int m = 0; m < 32; m++) {
            C[(gmr + m) * (long)ND + n0 + lane] = wbuf[m * 33 + lane] + bv;
        }
        __syncwarp();
    }
}

// ----------------------------- launch --------------------------------------
extern "C" void kernel_launch(void* const* d_in, const int* in_sizes, int n_in,
                              void* d_out, int out_size)
{
    const float* x      = (const float*)d_in[0];
    const float* weight = (const float*)d_in[1];
    const float* bias   = (const float*)d_in[2];
    const float* scores = (const float*)d_in[3];
    const float* noise  = (const float*)d_in[4];
    float* out = (float*)d_out;

    const int M = in_sizes[0] / KD;   // 16384

    cudaFuncSetAttribute(gemm_kernel,
                         cudaFuncAttributeMaxDynamicSharedMemorySize, SMEM_GEMM);

    pack_x<<<dim3(NKT, M / 128), 256>>>(x);
    pack_w<<<dim3(NKT, ND / 128), 256>>>(weight, scores, noise);

    dim3 grid(ND / 128, M / 128);     // (nb=32, mb=128)
    gemm_kernel<<<grid, 256, SMEM_GEMM>>>(bias, out);
}